// round 8
// baseline (speedup 1.0000x reference)
#include <cuda_runtime.h>
#include <math.h>
#include <stdint.h>

// Problem constants
#define BATCH 8
#define MCH   63
#define HW    307200
#define NBLK  80          // stats blocks per batch
#define CHUNK 3840        // HW / NBLK
#define SUB   1280
#define NSUB  3
#define PPT   5           // 256*5 = 1280
#define NV    16

typedef unsigned long long u64t;

// Scratch (device globals; no allocation allowed)
__device__ float g_partA[BATCH * NBLK * 4096];
__device__ float g_partX[BATCH * NBLK * 64];
__device__ float g_partS[BATCH * NBLK * 2];
__device__ float g_fit[BATCH * (4096 + 64)];   // per-batch G (lower tri, /sqrt(beta), 0 above) then w

// ---------------------------------------------------------------------------
// Kernel 1: sparse masked Gram accumulation (double-buffered gather).
// ---------------------------------------------------------------------------
__global__ void __launch_bounds__(256) stats_kernel(const float* __restrict__ bases,
                                                    const float* __restrict__ targets)
{
    const int b   = blockIdx.x / NBLK;
    const int blk = blockIdx.x % NBLK;
    const float* tgb = targets + (size_t)b * HW;
    const float* bs  = bases   + (size_t)b * MCH * HW;

    __shared__ int   pix [SUB];
    __shared__ float yls [SUB];
    __shared__ float bv  [2][NV][64];
    __shared__ float yg  [2][NV];
    __shared__ int   scan[256];

    const int tid = threadIdx.x;
    const int ti  = tid >> 4;
    const int tj  = tid & 15;

    float acc[4][4];
#pragma unroll
    for (int i = 0; i < 4; i++)
#pragma unroll
        for (int j = 0; j < 4; j++) acc[i][j] = 0.f;

    float xty = 0.f, yty = 0.f, ncnt = 0.f;

    for (int s = 0; s < NSUB; s++) {
        const int base = blk * CHUNK + s * SUB;
        const int p0   = base + tid * PPT;

        int cnt = 0;
#pragma unroll
        for (int k = 0; k < PPT; k++) {
            float y = tgb[p0 + k];
            if (isfinite(y)) cnt++;
        }
        scan[tid] = cnt;
        __syncthreads();
        for (int off = 1; off < 256; off <<= 1) {
            int v = (tid >= off) ? scan[tid - off] : 0;
            __syncthreads();
            scan[tid] += v;
            __syncthreads();
        }
        int wo    = scan[tid] - cnt;
        int total = scan[255];
        __syncthreads();

#pragma unroll
        for (int k = 0; k < PPT; k++) {
            float y = tgb[p0 + k];
            if (isfinite(y)) { pix[wo] = p0 + k; yls[wo] = y; wo++; }
        }
        __syncthreads();

        if (tid == 0) ncnt += (float)total;

        const int ng = (total + NV - 1) / NV;

        if (ng > 0) {
#pragma unroll
            for (int r = 0; r < 4; r++) {
                int idx = r * 256 + tid;
                int v = idx >> 6, c = idx & 63;
                float val = 0.f;
                if (v < total)
                    val = (c == 0) ? 1.f : bs[(size_t)(c - 1) * HW + pix[v]];
                bv[0][v][c] = val;
            }
            if (tid < NV) yg[0][tid] = (tid < total) ? yls[tid] : 0.f;
        }
        __syncthreads();

        for (int g = 0; g < ng; g++) {
            const int cur = g & 1;
            if (g + 1 < ng) {
                const int nxt = cur ^ 1;
                const int bnv = (g + 1) * NV;
#pragma unroll
                for (int r = 0; r < 4; r++) {
                    int idx = r * 256 + tid;
                    int v = idx >> 6, c = idx & 63;
                    int gv = bnv + v;
                    float val = 0.f;
                    if (gv < total)
                        val = (c == 0) ? 1.f : bs[(size_t)(c - 1) * HW + pix[gv]];
                    bv[nxt][v][c] = val;
                }
                if (tid < NV) {
                    int gv = bnv + tid;
                    yg[nxt][tid] = (gv < total) ? yls[gv] : 0.f;
                }
            }

            const float4* bv4 = (const float4*)bv[cur];
#pragma unroll
            for (int v = 0; v < NV; v++) {
                float4 R = bv4[v * 16 + ti];
                float4 C = bv4[v * 16 + tj];
                acc[0][0] += R.x * C.x; acc[0][1] += R.x * C.y; acc[0][2] += R.x * C.z; acc[0][3] += R.x * C.w;
                acc[1][0] += R.y * C.x; acc[1][1] += R.y * C.y; acc[1][2] += R.y * C.z; acc[1][3] += R.y * C.w;
                acc[2][0] += R.z * C.x; acc[2][1] += R.z * C.y; acc[2][2] += R.z * C.z; acc[2][3] += R.z * C.w;
                acc[3][0] += R.w * C.x; acc[3][1] += R.w * C.y; acc[3][2] += R.w * C.z; acc[3][3] += R.w * C.w;
            }
            if (tid < 64) {
#pragma unroll
                for (int v = 0; v < NV; v++) xty += bv[cur][v][tid] * yg[cur][v];
            }
            if (tid == 64) {
#pragma unroll
                for (int v = 0; v < NV; v++) yty += yg[cur][v] * yg[cur][v];
            }
            __syncthreads();
        }
        __syncthreads();
    }

    float* pa = g_partA + ((size_t)b * NBLK + blk) * 4096;
#pragma unroll
    for (int i = 0; i < 4; i++)
#pragma unroll
        for (int j = 0; j < 4; j++)
            pa[(ti * 4 + i) * 64 + (tj * 4 + j)] = acc[i][j];
    if (tid < 64)  g_partX[((size_t)b * NBLK + blk) * 64 + tid] = xty;
    if (tid == 64) g_partS[((size_t)b * NBLK + blk) * 2 + 0] = yty;
    if (tid == 0)  g_partS[((size_t)b * NBLK + blk) * 2 + 1] = ncnt;
}

// ---------------------------------------------------------------------------
// Kernel 2: per-batch reduce + Cholesky + solves + beta recurrence + L^-1.
// ---------------------------------------------------------------------------
__global__ void __launch_bounds__(256) solve_kernel(float* __restrict__ out)
{
    const int b   = blockIdx.x;
    const int tid = threadIdx.x;

    __shared__ float A [64 * 65];
    __shared__ float Li[64 * 65];
    __shared__ float xty[64], wv[64], zv[64];
    __shared__ float sc[4];

    for (int e = tid; e < 4096; e += 256) {
        float s = 0.f;
#pragma unroll 4
        for (int k = 0; k < NBLK; k++) s += g_partA[((size_t)b * NBLK + k) * 4096 + e];
        A[(e >> 6) * 65 + (e & 63)] = s;
    }
    if (tid < 64) {
        float s = 0.f;
#pragma unroll 4
        for (int k = 0; k < NBLK; k++) s += g_partX[((size_t)b * NBLK + k) * 64 + tid];
        xty[tid] = s;
    }
    if (tid == 0) {
        float yt = 0.f, n = 0.f;
        for (int k = 0; k < NBLK; k++) {
            yt += g_partS[((size_t)b * NBLK + k) * 2 + 0];
            n  += g_partS[((size_t)b * NBLK + k) * 2 + 1];
        }
        sc[0] = yt; sc[1] = n;
    }
    __syncthreads();

    for (int k = 0; k < 64; k++) {
        if (tid == 0) A[k * 65 + k] = sqrtf(A[k * 65 + k]);
        __syncthreads();
        if (tid > k && tid < 64) A[tid * 65 + k] /= A[k * 65 + k];
        __syncthreads();
        if (tid > k && tid < 64) {
            float l = A[tid * 65 + k];
            for (int i = k + 1; i <= tid; i++) A[tid * 65 + i] -= l * A[i * 65 + k];
        }
        __syncthreads();
    }

    if (tid < 64) zv[tid] = xty[tid];
    __syncthreads();
    for (int k = 0; k < 64; k++) {
        if (tid == k) zv[k] /= A[k * 65 + k];
        __syncthreads();
        if (tid > k && tid < 64) zv[tid] -= A[tid * 65 + k] * zv[k];
        __syncthreads();
    }
    if (tid < 64) wv[tid] = zv[tid];
    __syncthreads();
    for (int k = 63; k >= 0; k--) {
        if (tid == k) wv[k] /= A[k * 65 + k];
        __syncthreads();
        if (tid < k) wv[tid] -= A[k * 65 + tid] * wv[k];
        __syncthreads();
    }

    if (tid == 0) {
        float yt = sc[0], n = sc[1];
        float wx = 0.f, zz = 0.f;
        for (int c = 0; c < 64; c++) { wx += wv[c] * xty[c]; zz += zv[c] * zv[c]; }
        float E = yt - 2.f * wx + zz;
        float beta0 = sqrtf(n), beta = beta0;
        bool done = false;
        for (int it = 0; it < 5; it++) {
            float bn   = n / (E + 64.f / beta);
            bool  conv = fabsf(bn / beta0 - 1.f) < 0.02f;
            if (!done) { beta = bn; beta0 = bn; }
            done = done || conv;
        }
        sc[2] = beta;
    }
    __syncthreads();

    if (tid < 64) {
        const int c = tid;
        for (int k = c; k < 64; k++) {
            float s = (k == c) ? 1.f : 0.f;
            for (int j = c; j < k; j++) s -= A[k * 65 + j] * Li[j * 65 + c];
            Li[k * 65 + c] = s / A[k * 65 + k];
        }
    }
    __syncthreads();

    const float sb = rsqrtf(sc[2]);
    float* G = g_fit + (size_t)b * (4096 + 64);
    for (int e = tid; e < 4096; e += 256) {
        int i = e >> 6, j = e & 63;
        G[e] = (j <= i) ? Li[i * 65 + j] * sb : 0.f;
    }
    if (tid < 64) {
        G[4096 + tid] = wv[tid];
        out[(size_t)BATCH * HW + (size_t)b * 64 + tid] = wv[tid];
    }
}

// ---------------------------------------------------------------------------
// Kernel 3: per-pixel prediction + variance with CHANNEL-pair f32x2 packing.
// One pixel per thread (64 b32 regs of basis). Each f32x2 lane = channels
// (2j, 2j+1) of the same row dot product; row reduce = free unpack + 1 FADD.
// G's natural fp32 row layout IS the packed layout (no duplication, 16 KB).
// Zero padding above the diagonal makes the 4-column granularity safe.
// ---------------------------------------------------------------------------
__device__ __forceinline__ void fma2(u64t& d, u64t a, u64t b) {
    asm("fma.rn.f32x2 %0, %1, %2, %0;" : "+l"(d) : "l"(a), "l"(b));
}
__device__ __forceinline__ float hsum2(u64t v) {
    unsigned lo, hi;
    asm("mov.b64 {%0, %1}, %2;" : "=r"(lo), "=r"(hi) : "l"(v));
    return __uint_as_float(lo) + __uint_as_float(hi);
}
__device__ __forceinline__ u64t pack2(float lo, float hi) {
    u64t r;
    asm("mov.b64 %0, {%1, %2};" : "=l"(r) : "r"(__float_as_uint(lo)), "r"(__float_as_uint(hi)));
    return r;
}

#define ROW(I) do {                                                          \
    u64t t2 = 0ull;                                                          \
    _Pragma("unroll")                                                        \
    for (int j4 = 0; j4 <= ((I) >> 2); ++j4) {                               \
        ulonglong2 g = Gs2[(I) * 16 + j4];                                   \
        fma2(t2, g.x, bv2[2 * j4]);                                          \
        fma2(t2, g.y, bv2[2 * j4 + 1]);                                      \
    }                                                                        \
    float tt = hsum2(t2);                                                    \
    var = fmaf(tt, tt, var);                                                 \
} while (0)

#define ROW4(I) ROW(I); ROW((I) + 1); ROW((I) + 2); ROW((I) + 3)

__global__ void __launch_bounds__(256, 2) pred_kernel(const float* __restrict__ bases,
                                                      float* __restrict__ out)
{
    const int blocks_per_batch = HW / 256;   // 1200
    const int b   = blockIdx.x / blocks_per_batch;
    const int blk = blockIdx.x % blocks_per_batch;

    __shared__ float Gs[4096];   // 16 KB: G rows fp32 (packed pairs by aliasing)
    __shared__ float ws[64];

    const float* fit = g_fit + (size_t)b * (4096 + 64);
    {
        float4* Gs4 = (float4*)Gs;
        const float4* fit4 = (const float4*)fit;
#pragma unroll
        for (int r = 0; r < 4; r++) Gs4[r * 256 + threadIdx.x] = fit4[r * 256 + threadIdx.x];
        if (threadIdx.x < 64) ws[threadIdx.x] = fit[4096 + threadIdx.x];
    }
    __syncthreads();

    const ulonglong2* Gs2 = (const ulonglong2*)Gs;   // Gs2[i*16 + j4] = 4 floats of row i
    const u64t*       ws2 = (const u64t*)ws;

    const float* bs = bases + (size_t)b * MCH * HW;
    const int p = blk * 256 + threadIdx.x;

    // basis in packed channel pairs: bv2[c2] = {ch[2c2], ch[2c2+1]}
    u64t bv2[32];
    bv2[0] = pack2(1.f, __ldg(bs + p));              // ch0 = ones, ch1 = bs[0]
#pragma unroll
    for (int c2 = 1; c2 < 32; c2++)
        bv2[c2] = pack2(__ldg(bs + (size_t)(2 * c2 - 1) * HW + p),
                        __ldg(bs + (size_t)(2 * c2)     * HW + p));

    // prediction (packed dot)
    u64t pred2 = 0ull;
#pragma unroll
    for (int c2 = 0; c2 < 32; c2++) fma2(pred2, ws2[c2], bv2[c2]);
    const float pred = hsum2(pred2);

    // variance: || G b ||^2, triangular rows fully unrolled, packed channels
    float var = 0.f;
    ROW4(0);  ROW4(4);  ROW4(8);  ROW4(12);
    ROW4(16); ROW4(20); ROW4(24); ROW4(28);
    ROW4(32); ROW4(36); ROW4(40); ROW4(44);
    ROW4(48); ROW4(52); ROW4(56); ROW4(60);

    out[(size_t)b * HW + p] = pred;
    out[(size_t)BATCH * HW + (size_t)BATCH * 64 + (size_t)b * HW + p] = var;
}

// ---------------------------------------------------------------------------
extern "C" void kernel_launch(void* const* d_in, const int* in_sizes, int n_in,
                              void* d_out, int out_size)
{
    const float* bases   = (const float*)d_in[0];
    const float* targets = (const float*)d_in[1];
    if (n_in >= 2 && in_sizes[0] < in_sizes[1]) {
        const float* t = bases; bases = targets; targets = t;
    }
    float* out = (float*)d_out;

    stats_kernel<<<BATCH * NBLK, 256>>>(bases, targets);
    solve_kernel<<<BATCH, 256>>>(out);
    pred_kernel<<<BATCH * (HW / 256), 256>>>(bases, out);
}

// round 9
// speedup vs baseline: 1.4001x; 1.4001x over previous
#include <cuda_runtime.h>
#include <cuda_bf16.h>
#include <math.h>
#include <stdint.h>

// Problem constants
#define BATCH 8
#define MCH   63
#define HW    307200
#define NBLK  80          // stats blocks per batch
#define CHUNK 3840        // HW / NBLK
#define SUB   1280
#define NSUB  3
#define PPT   5           // 256*5 = 1280
#define NV    16

// pred mma constants
#define NTILES     9       // 8 G-row tiles + 1 w tile (N = 72)
#define KSTEPS     4       // K = 64 channels, 16 per mma
#define BFRAG_SZ   (NTILES * KSTEPS * 32 * 4)   // u32 per batch = 4608
#define PRED_CTAS  150     // per batch; 150 * 2048 px = HW
#define PX_PER_CTA 2048
#define ROUNDS     16      // 2048 / (8 warps * 16 px)

// Scratch (device globals; no allocation allowed)
__device__ float    g_partA[BATCH * NBLK * 4096];
__device__ float    g_partX[BATCH * NBLK * 64];
__device__ float    g_partS[BATCH * NBLK * 2];
__device__ float    g_fit[BATCH * (4096 + 64)];
__device__ uint32_t g_bfrag[BATCH * BFRAG_SZ];   // per-lane B fragments (hi/lo bf16 pairs)

// ---------------- small helpers ----------------
__device__ __forceinline__ uint32_t pack_bf2(float lo_elem, float hi_elem) {
    // result: low 16 bits = bf16(lo_elem), high 16 bits = bf16(hi_elem)
    uint32_t r;
    asm("cvt.rn.bf16x2.f32 %0, %1, %2;" : "=r"(r) : "f"(hi_elem), "f"(lo_elem));
    return r;
}
__device__ __forceinline__ void mma16816(float* c, const uint32_t* a, uint32_t b0, uint32_t b1) {
    asm volatile(
        "mma.sync.aligned.m16n8k16.row.col.f32.bf16.bf16.f32 "
        "{%0,%1,%2,%3}, {%4,%5,%6,%7}, {%8,%9}, {%0,%1,%2,%3};"
        : "+f"(c[0]), "+f"(c[1]), "+f"(c[2]), "+f"(c[3])
        : "r"(a[0]), "r"(a[1]), "r"(a[2]), "r"(a[3]), "r"(b0), "r"(b1));
}

// ---------------------------------------------------------------------------
// Kernel 1: sparse masked Gram accumulation (double-buffered gather).
// ---------------------------------------------------------------------------
__global__ void __launch_bounds__(256) stats_kernel(const float* __restrict__ bases,
                                                    const float* __restrict__ targets)
{
    const int b   = blockIdx.x / NBLK;
    const int blk = blockIdx.x % NBLK;
    const float* tgb = targets + (size_t)b * HW;
    const float* bs  = bases   + (size_t)b * MCH * HW;

    __shared__ int   pix [SUB];
    __shared__ float yls [SUB];
    __shared__ float bv  [2][NV][64];
    __shared__ float yg  [2][NV];
    __shared__ int   scan[256];

    const int tid = threadIdx.x;
    const int ti  = tid >> 4;
    const int tj  = tid & 15;

    float acc[4][4];
#pragma unroll
    for (int i = 0; i < 4; i++)
#pragma unroll
        for (int j = 0; j < 4; j++) acc[i][j] = 0.f;

    float xty = 0.f, yty = 0.f, ncnt = 0.f;

    for (int s = 0; s < NSUB; s++) {
        const int base = blk * CHUNK + s * SUB;
        const int p0   = base + tid * PPT;

        int cnt = 0;
#pragma unroll
        for (int k = 0; k < PPT; k++) {
            float y = tgb[p0 + k];
            if (isfinite(y)) cnt++;
        }
        scan[tid] = cnt;
        __syncthreads();
        for (int off = 1; off < 256; off <<= 1) {
            int v = (tid >= off) ? scan[tid - off] : 0;
            __syncthreads();
            scan[tid] += v;
            __syncthreads();
        }
        int wo    = scan[tid] - cnt;
        int total = scan[255];
        __syncthreads();

#pragma unroll
        for (int k = 0; k < PPT; k++) {
            float y = tgb[p0 + k];
            if (isfinite(y)) { pix[wo] = p0 + k; yls[wo] = y; wo++; }
        }
        __syncthreads();

        if (tid == 0) ncnt += (float)total;

        const int ng = (total + NV - 1) / NV;

        if (ng > 0) {
#pragma unroll
            for (int r = 0; r < 4; r++) {
                int idx = r * 256 + tid;
                int v = idx >> 6, c = idx & 63;
                float val = 0.f;
                if (v < total)
                    val = (c == 0) ? 1.f : bs[(size_t)(c - 1) * HW + pix[v]];
                bv[0][v][c] = val;
            }
            if (tid < NV) yg[0][tid] = (tid < total) ? yls[tid] : 0.f;
        }
        __syncthreads();

        for (int g = 0; g < ng; g++) {
            const int cur = g & 1;
            if (g + 1 < ng) {
                const int nxt = cur ^ 1;
                const int bnv = (g + 1) * NV;
#pragma unroll
                for (int r = 0; r < 4; r++) {
                    int idx = r * 256 + tid;
                    int v = idx >> 6, c = idx & 63;
                    int gv = bnv + v;
                    float val = 0.f;
                    if (gv < total)
                        val = (c == 0) ? 1.f : bs[(size_t)(c - 1) * HW + pix[gv]];
                    bv[nxt][v][c] = val;
                }
                if (tid < NV) {
                    int gv = bnv + tid;
                    yg[nxt][tid] = (gv < total) ? yls[gv] : 0.f;
                }
            }

            const float4* bv4 = (const float4*)bv[cur];
#pragma unroll
            for (int v = 0; v < NV; v++) {
                float4 R = bv4[v * 16 + ti];
                float4 C = bv4[v * 16 + tj];
                acc[0][0] += R.x * C.x; acc[0][1] += R.x * C.y; acc[0][2] += R.x * C.z; acc[0][3] += R.x * C.w;
                acc[1][0] += R.y * C.x; acc[1][1] += R.y * C.y; acc[1][2] += R.y * C.z; acc[1][3] += R.y * C.w;
                acc[2][0] += R.z * C.x; acc[2][1] += R.z * C.y; acc[2][2] += R.z * C.z; acc[2][3] += R.z * C.w;
                acc[3][0] += R.w * C.x; acc[3][1] += R.w * C.y; acc[3][2] += R.w * C.z; acc[3][3] += R.w * C.w;
            }
            if (tid < 64) {
#pragma unroll
                for (int v = 0; v < NV; v++) xty += bv[cur][v][tid] * yg[cur][v];
            }
            if (tid == 64) {
#pragma unroll
                for (int v = 0; v < NV; v++) yty += yg[cur][v] * yg[cur][v];
            }
            __syncthreads();
        }
        __syncthreads();
    }

    float* pa = g_partA + ((size_t)b * NBLK + blk) * 4096;
#pragma unroll
    for (int i = 0; i < 4; i++)
#pragma unroll
        for (int j = 0; j < 4; j++)
            pa[(ti * 4 + i) * 64 + (tj * 4 + j)] = acc[i][j];
    if (tid < 64)  g_partX[((size_t)b * NBLK + blk) * 64 + tid] = xty;
    if (tid == 64) g_partS[((size_t)b * NBLK + blk) * 2 + 0] = yty;
    if (tid == 0)  g_partS[((size_t)b * NBLK + blk) * 2 + 1] = ncnt;
}

// ---------------------------------------------------------------------------
// Kernel 2: reduce + Cholesky + solves + beta + L^-1 + per-lane B-fragment
// table for the mma pred kernel.
// ---------------------------------------------------------------------------
__global__ void __launch_bounds__(256) solve_kernel(float* __restrict__ out)
{
    const int b   = blockIdx.x;
    const int tid = threadIdx.x;

    __shared__ float A [64 * 65];
    __shared__ float Li[64 * 65];
    __shared__ float xty[64], wv[64], zv[64];
    __shared__ float sc[4];

    for (int e = tid; e < 4096; e += 256) {
        float s = 0.f;
#pragma unroll 4
        for (int k = 0; k < NBLK; k++) s += g_partA[((size_t)b * NBLK + k) * 4096 + e];
        A[(e >> 6) * 65 + (e & 63)] = s;
    }
    if (tid < 64) {
        float s = 0.f;
#pragma unroll 4
        for (int k = 0; k < NBLK; k++) s += g_partX[((size_t)b * NBLK + k) * 64 + tid];
        xty[tid] = s;
    }
    if (tid == 0) {
        float yt = 0.f, n = 0.f;
        for (int k = 0; k < NBLK; k++) {
            yt += g_partS[((size_t)b * NBLK + k) * 2 + 0];
            n  += g_partS[((size_t)b * NBLK + k) * 2 + 1];
        }
        sc[0] = yt; sc[1] = n;
    }
    __syncthreads();

    for (int k = 0; k < 64; k++) {
        if (tid == 0) A[k * 65 + k] = sqrtf(A[k * 65 + k]);
        __syncthreads();
        if (tid > k && tid < 64) A[tid * 65 + k] /= A[k * 65 + k];
        __syncthreads();
        if (tid > k && tid < 64) {
            float l = A[tid * 65 + k];
            for (int i = k + 1; i <= tid; i++) A[tid * 65 + i] -= l * A[i * 65 + k];
        }
        __syncthreads();
    }

    if (tid < 64) zv[tid] = xty[tid];
    __syncthreads();
    for (int k = 0; k < 64; k++) {
        if (tid == k) zv[k] /= A[k * 65 + k];
        __syncthreads();
        if (tid > k && tid < 64) zv[tid] -= A[tid * 65 + k] * zv[k];
        __syncthreads();
    }
    if (tid < 64) wv[tid] = zv[tid];
    __syncthreads();
    for (int k = 63; k >= 0; k--) {
        if (tid == k) wv[k] /= A[k * 65 + k];
        __syncthreads();
        if (tid < k) wv[tid] -= A[k * 65 + tid] * wv[k];
        __syncthreads();
    }

    if (tid == 0) {
        float yt = sc[0], n = sc[1];
        float wx = 0.f, zz = 0.f;
        for (int c = 0; c < 64; c++) { wx += wv[c] * xty[c]; zz += zv[c] * zv[c]; }
        float E = yt - 2.f * wx + zz;
        float beta0 = sqrtf(n), beta = beta0;
        bool done = false;
        for (int it = 0; it < 5; it++) {
            float bn   = n / (E + 64.f / beta);
            bool  conv = fabsf(bn / beta0 - 1.f) < 0.02f;
            if (!done) { beta = bn; beta0 = bn; }
            done = done || conv;
        }
        sc[2] = beta;
    }
    __syncthreads();

    if (tid < 64) {
        const int c = tid;
        for (int k = c; k < 64; k++) {
            float s = (k == c) ? 1.f : 0.f;
            for (int j = c; j < k; j++) s -= A[k * 65 + j] * Li[j * 65 + c];
            Li[k * 65 + c] = s / A[k * 65 + k];
        }
    }
    __syncthreads();

    const float sb = rsqrtf(sc[2]);
    if (tid < 64) out[(size_t)BATCH * HW + (size_t)b * 64 + tid] = wv[tid];

    // ---- B-fragment table: idx = ((nt*4 + ks)*32 + lane)*4 + j ----
    // n = nt*8 + lane/4 ; k0 = ks*16 + (lane%4)*2 + (j&1)*8 ; part = j>>1
    // rows: n<64 -> G[n][k] = (k<=n ? Li*sb : 0); n==64 -> w[k]; n>64 -> 0
    uint32_t* tabb = g_bfrag + (size_t)b * BFRAG_SZ;
    for (int e = tid; e < BFRAG_SZ; e += 256) {
        int j    = e & 3;
        int lane = (e >> 2) & 31;
        int ks   = (e >> 7) & 3;
        int nt   = e >> 9;
        int n    = nt * 8 + (lane >> 2);
        int k0   = ks * 16 + (lane & 3) * 2 + ((j & 1) ? 8 : 0);

        float v0, v1;
        if (n < 64) {
            v0 = (k0     <= n) ? Li[n * 65 + k0]     * sb : 0.f;
            v1 = (k0 + 1 <= n) ? Li[n * 65 + k0 + 1] * sb : 0.f;
        } else if (n == 64) {
            v0 = wv[k0]; v1 = wv[k0 + 1];
        } else {
            v0 = 0.f; v1 = 0.f;
        }
        uint32_t r;
        if ((j >> 1) == 0) {
            r = pack_bf2(v0, v1);                      // hi parts
        } else {
            float h0 = __bfloat162float(__float2bfloat16(v0));
            float h1 = __bfloat162float(__float2bfloat16(v1));
            r = pack_bf2(v0 - h0, v1 - h1);            // lo parts
        }
        tabb[e] = r;
    }
}

// ---------------------------------------------------------------------------
// Kernel 3: pred + var via mma.sync bf16 3-term split.
// D[px, n] = sum_c b[px][c] * G[n][c], n<64: var rows, n=64: w.
// Each warp: 16 pixels (M=16), 9 n-tiles, K=64 in 4 steps, 3 split passes.
// A built in registers from coalesced LDG; B fragments from precomputed table.
// ---------------------------------------------------------------------------
__global__ void __launch_bounds__(256) pred_mma_kernel(const float* __restrict__ bases,
                                                       float* __restrict__ out)
{
    __shared__ uint32_t Bsm[BFRAG_SZ];   // 18.4 KB

    const int b    = blockIdx.x / PRED_CTAS;
    const int cta  = blockIdx.x % PRED_CTAS;
    const int tid  = threadIdx.x;
    const int wid  = tid >> 5;
    const int lane = tid & 31;
    const int g    = lane >> 2;   // 0..7 (pixel within half-tile / B row)
    const int t    = lane & 3;    // 0..3 (k/col group)

    {
        const uint32_t* src = g_bfrag + (size_t)b * BFRAG_SZ;
        for (int e = tid; e < BFRAG_SZ; e += 256) Bsm[e] = src[e];
    }
    __syncthreads();
    const uint4* Bs4 = (const uint4*)Bsm;   // Bs4[(nt*4+ks)*32 + lane] = {BH0,BH1,BL0,BL1}

    const float* bs   = bases + (size_t)b * MCH * HW;
    float* outL = out + (size_t)b * HW;
    float* outV = out + (size_t)BATCH * HW + (size_t)BATCH * 64 + (size_t)b * HW;

    for (int r = 0; r < ROUNDS; r++) {
        const int px0 = cta * PX_PER_CTA + r * 128 + wid * 16;   // warp's 16 pixels
        const int pA  = px0 + g;
        const int pB  = pA + 8;

        float C[NTILES][4];
#pragma unroll
        for (int n = 0; n < NTILES; n++)
#pragma unroll
            for (int q = 0; q < 4; q++) C[n][q] = 0.f;

#pragma unroll
        for (int ks = 0; ks < KSTEPS; ks++) {
            const int cA = ks * 16 + t * 2;   // channels cA, cA+1, cA+8, cA+9

            // load 8 basis floats (channel 0 is the implicit ones channel)
            float fA0 = (cA == 0) ? 1.f : __ldg(bs + (size_t)(cA - 1) * HW + pA);
            float fA1 = __ldg(bs + (size_t)(cA    ) * HW + pA);
            float fA2 = __ldg(bs + (size_t)(cA + 7) * HW + pA);
            float fA3 = __ldg(bs + (size_t)(cA + 8) * HW + pA);
            float fB0 = (cA == 0) ? 1.f : __ldg(bs + (size_t)(cA - 1) * HW + pB);
            float fB1 = __ldg(bs + (size_t)(cA    ) * HW + pB);
            float fB2 = __ldg(bs + (size_t)(cA + 7) * HW + pB);
            float fB3 = __ldg(bs + (size_t)(cA + 8) * HW + pB);

            uint32_t Ah[4], Al[4];
            Ah[0] = pack_bf2(fA0, fA1);
            Ah[1] = pack_bf2(fB0, fB1);
            Ah[2] = pack_bf2(fA2, fA3);
            Ah[3] = pack_bf2(fB2, fB3);
            {
                float h;
                h = __uint_as_float(Ah[0] << 16);          float lA0 = fA0 - h;
                h = __uint_as_float(Ah[0] & 0xFFFF0000u);  float lA1 = fA1 - h;
                h = __uint_as_float(Ah[1] << 16);          float lB0 = fB0 - h;
                h = __uint_as_float(Ah[1] & 0xFFFF0000u);  float lB1 = fB1 - h;
                h = __uint_as_float(Ah[2] << 16);          float lA2 = fA2 - h;
                h = __uint_as_float(Ah[2] & 0xFFFF0000u);  float lA3 = fA3 - h;
                h = __uint_as_float(Ah[3] << 16);          float lB2 = fB2 - h;
                h = __uint_as_float(Ah[3] & 0xFFFF0000u);  float lB3 = fB3 - h;
                Al[0] = pack_bf2(lA0, lA1);
                Al[1] = pack_bf2(lB0, lB1);
                Al[2] = pack_bf2(lA2, lA3);
                Al[3] = pack_bf2(lB2, lB3);
            }

#pragma unroll
            for (int nt = 0; nt < NTILES; nt++) {
                uint4 q = Bs4[(nt * 4 + ks) * 32 + lane];
                mma16816(C[nt], Ah, q.x, q.y);   // hi * hi
                mma16816(C[nt], Ah, q.z, q.w);   // hi * lo
                mma16816(C[nt], Al, q.x, q.y);   // lo * hi
            }
        }

        // epilogue: var = sum over n<64 of D^2 ; pred = D[., 64]
        float vA = 0.f, vB = 0.f;
#pragma unroll
        for (int nt = 0; nt < 8; nt++) {
            vA = fmaf(C[nt][0], C[nt][0], vA);
            vA = fmaf(C[nt][1], C[nt][1], vA);
            vB = fmaf(C[nt][2], C[nt][2], vB);
            vB = fmaf(C[nt][3], C[nt][3], vB);
        }
        vA += __shfl_xor_sync(0xFFFFFFFFu, vA, 1);
        vA += __shfl_xor_sync(0xFFFFFFFFu, vA, 2);
        vB += __shfl_xor_sync(0xFFFFFFFFu, vB, 1);
        vB += __shfl_xor_sync(0xFFFFFFFFu, vB, 2);

        if (t == 0) {
            outL[pA] = C[8][0];   // n = 64 (w row)
            outL[pB] = C[8][2];
            outV[pA] = vA;
            outV[pB] = vB;
        }
    }
}

// ---------------------------------------------------------------------------
extern "C" void kernel_launch(void* const* d_in, const int* in_sizes, int n_in,
                              void* d_out, int out_size)
{
    const float* bases   = (const float*)d_in[0];
    const float* targets = (const float*)d_in[1];
    if (n_in >= 2 && in_sizes[0] < in_sizes[1]) {
        const float* t = bases; bases = targets; targets = t;
    }
    float* out = (float*)d_out;

    stats_kernel<<<BATCH * NBLK, 256>>>(bases, targets);
    solve_kernel<<<BATCH, 256>>>(out);
    pred_mma_kernel<<<BATCH * PRED_CTAS, 256>>>(bases, out);
}